// round 1
// baseline (speedup 1.0000x reference)
#include <cuda_runtime.h>
#include <cuda_bf16.h>
#include <cstdint>

// Inputs (metadata order):
// 0: stimulus_set int32 [B,5]
// 1: table        f32   [21,3]
// 2: w            f32   [3]
// 3: rho f32[1]  4: beta f32[1]  5: tau f32[1]  6: gamma f32[1]
// 7: upper f32[1] 8: midpoint f32[1] 9: rate f32[1]
// Output: concat(output_rank [B,4], output_rt [B,1]) f32, out_size = 5*B

#define ROWS_PER_THREAD 4

__global__ __launch_bounds__(256) void rankrt_kernel(
    const int4* __restrict__ stim4,      // [B*5/4] int4 view
    const float* __restrict__ table,     // [21*3]
    const float* __restrict__ w,
    const float* __restrict__ rho_p, const float* __restrict__ beta_p,
    const float* __restrict__ tau_p, const float* __restrict__ gamma_p,
    const float* __restrict__ upper_p, const float* __restrict__ midpoint_p,
    const float* __restrict__ rate_p,
    float* __restrict__ rank_out,        // [B*4]
    float* __restrict__ rt_out,          // [B]
    int n_threads)                       // B / ROWS_PER_THREAD
{
    __shared__ float st[64];             // 21*3 = 63 floats
    if (threadIdx.x < 63) st[threadIdx.x] = table[threadIdx.x];
    __syncthreads();

    int t = blockIdx.x * blockDim.x + threadIdx.x;
    if (t >= n_threads) return;

    const float w0 = __ldg(w), w1 = __ldg(w + 1), w2 = __ldg(w + 2);
    const float rho = __ldg(rho_p), beta = __ldg(beta_p), tau = __ldg(tau_p);
    const float gamma = __ldg(gamma_p), upper = __ldg(upper_p);
    const float midpoint = __ldg(midpoint_p), rate = __ldg(rate_p);
    const bool rho2 = (rho == 2.0f);
    const bool tau1 = (tau == 1.0f);
    const float inv_rho = 1.0f / rho;

    // 4 rows * 5 ints = 20 ints = 5 int4 loads, base byte offset t*80 (16-aligned)
    int idx[20];
    #pragma unroll
    for (int v = 0; v < 5; v++) {
        int4 p = stim4[t * 5 + v];
        idx[v * 4 + 0] = p.x; idx[v * 4 + 1] = p.y;
        idx[v * 4 + 2] = p.z; idx[v * 4 + 3] = p.w;
    }

    float rt4[ROWS_PER_THREAD];

    #pragma unroll
    for (int r = 0; r < ROWS_PER_THREAD; r++) {
        const int* row = idx + r * 5;
        int q = row[0];
        float zq0 = st[q * 3 + 0], zq1 = st[q * 3 + 1], zq2 = st[q * 3 + 2];

        float s[4], ssum = 0.0f;
        #pragma unroll
        for (int k = 0; k < 4; k++) {
            int ri = row[1 + k];
            float dx = fabsf(zq0 - st[ri * 3 + 0]);
            float dy = fabsf(zq1 - st[ri * 3 + 1]);
            float dz = fabsf(zq2 - st[ri * 3 + 2]);
            float d;
            if (rho2) {
                float dsq = fmaf(w0, dx * dx, fmaf(w1, dy * dy, w2 * dz * dz));
                d = sqrtf(dsq);
            } else {
                float acc = w0 * __powf(dx, rho) + w1 * __powf(dy, rho) + w2 * __powf(dz, rho);
                d = __powf(acc, inv_rho);
            }
            float dt = tau1 ? d : __powf(d, tau);
            s[k] = __expf(-beta * dt) + gamma;
            ssum += s[k];
        }

        float inv = __frcp_rn(ssum);
        float ent = 0.0f;
        float4 rv;
        float rk[4];
        #pragma unroll
        for (int k = 0; k < 4; k++) {
            rk[k] = s[k] * inv;
            ent -= rk[k] * __logf(rk[k]);
        }
        rv.x = rk[0]; rv.y = rk[1]; rv.z = rk[2]; rv.w = rk[3];
        reinterpret_cast<float4*>(rank_out)[t * ROWS_PER_THREAD + r] = rv;

        rt4[r] = upper * __frcp_rn(1.0f + __expf(-rate * (ent - midpoint)));
    }

    float4 rtv = make_float4(rt4[0], rt4[1], rt4[2], rt4[3]);
    reinterpret_cast<float4*>(rt_out)[t] = rtv;
}

extern "C" void kernel_launch(void* const* d_in, const int* in_sizes, int n_in,
                              void* d_out, int out_size) {
    const int* stim = (const int*)d_in[0];
    const float* table = (const float*)d_in[1];
    const float* w = (const float*)d_in[2];
    const float* rho_p = (const float*)d_in[3];
    const float* beta_p = (const float*)d_in[4];
    const float* tau_p = (const float*)d_in[5];
    const float* gamma_p = (const float*)d_in[6];
    const float* upper_p = (const float*)d_in[7];
    const float* midpoint_p = (const float*)d_in[8];
    const float* rate_p = (const float*)d_in[9];

    int B = in_sizes[0] / 5;
    float* rank_out = (float*)d_out;          // B*4
    float* rt_out = (float*)d_out + (size_t)B * 4;  // B

    int n_threads = B / ROWS_PER_THREAD;      // B=2,000,000 divisible by 4
    int block = 256;
    int grid = (n_threads + block - 1) / block;
    rankrt_kernel<<<grid, block>>>(
        (const int4*)stim, table, w, rho_p, beta_p, tau_p, gamma_p,
        upper_p, midpoint_p, rate_p, rank_out, rt_out, n_threads);
}

// round 2
// speedup vs baseline: 1.0139x; 1.0139x over previous
#include <cuda_runtime.h>
#include <cuda_bf16.h>
#include <cstdint>

// Inputs (metadata order):
// 0: stimulus_set int32 [B,5]
// 1: table        f32   [21,3]
// 2: w            f32   [3]
// 3: rho 4: beta 5: tau 6: gamma 7: upper 8: midpoint 9: rate  (all f32[1])
// Output: concat(output_rank [B,4], output_rt [B,1]) f32

#define ROWS_PER_THREAD 4
#define N_TAB 21
#define N_PAIRS (N_TAB * N_TAB)   // 441

__global__ __launch_bounds__(256) void rankrt_kernel(
    const int4* __restrict__ stim4,      // [B*5/4] int4 view
    const float* __restrict__ table,     // [21*3]
    const float* __restrict__ w,
    const float* __restrict__ rho_p, const float* __restrict__ beta_p,
    const float* __restrict__ tau_p, const float* __restrict__ gamma_p,
    const float* __restrict__ upper_p, const float* __restrict__ midpoint_p,
    const float* __restrict__ rate_p,
    float* __restrict__ rank_out,        // [B*4]
    float* __restrict__ rt_out,          // [B]
    int n_threads)                       // B / ROWS_PER_THREAD
{
    // pair_tab[q*21+r] = { s(q,r), s*log(s) }
    __shared__ float2 pair_tab[N_PAIRS];

    const float w0 = __ldg(w), w1 = __ldg(w + 1), w2 = __ldg(w + 2);
    const float rho = __ldg(rho_p), beta = __ldg(beta_p), tau = __ldg(tau_p);
    const float gamma = __ldg(gamma_p), upper = __ldg(upper_p);
    const float midpoint = __ldg(midpoint_p), rate = __ldg(rate_p);
    const bool rho2 = (rho == 2.0f);
    const bool tau1 = (tau == 1.0f);
    const float inv_rho = 1.0f / rho;

    // Per-block precompute of the 441-entry pair table (~2 entries/thread).
    for (int e = threadIdx.x; e < N_PAIRS; e += blockDim.x) {
        int q = e / N_TAB;
        int r = e - q * N_TAB;
        float dx = fabsf(__ldg(table + q * 3 + 0) - __ldg(table + r * 3 + 0));
        float dy = fabsf(__ldg(table + q * 3 + 1) - __ldg(table + r * 3 + 1));
        float dz = fabsf(__ldg(table + q * 3 + 2) - __ldg(table + r * 3 + 2));
        float d;
        if (rho2) {
            float dsq = fmaf(w0, dx * dx, fmaf(w1, dy * dy, w2 * dz * dz));
            d = sqrtf(dsq);
        } else {
            float acc = w0 * __powf(dx, rho) + w1 * __powf(dy, rho) + w2 * __powf(dz, rho);
            d = __powf(acc, inv_rho);
        }
        float dt = tau1 ? d : __powf(d, tau);
        float s = __expf(-beta * dt) + gamma;
        pair_tab[e] = make_float2(s, s * __logf(s));
    }
    __syncthreads();

    int t = blockIdx.x * blockDim.x + threadIdx.x;
    if (t >= n_threads) return;

    // 4 rows * 5 ints = 20 ints = 5 int4 loads (16B-aligned at t*80 bytes)
    int idx[20];
    #pragma unroll
    for (int v = 0; v < 5; v++) {
        int4 p = stim4[t * 5 + v];
        idx[v * 4 + 0] = p.x; idx[v * 4 + 1] = p.y;
        idx[v * 4 + 2] = p.z; idx[v * 4 + 3] = p.w;
    }

    float rt4[ROWS_PER_THREAD];

    #pragma unroll
    for (int r = 0; r < ROWS_PER_THREAD; r++) {
        const int* row = idx + r * 5;
        const float2* qrow = pair_tab + row[0] * N_TAB;

        float s0, s1, s2, s3, ssum, slsum;
        {
            float2 p0 = qrow[row[1]];
            float2 p1 = qrow[row[2]];
            float2 p2 = qrow[row[3]];
            float2 p3 = qrow[row[4]];
            s0 = p0.x; s1 = p1.x; s2 = p2.x; s3 = p3.x;
            ssum  = (p0.x + p1.x) + (p2.x + p3.x);
            slsum = (p0.y + p1.y) + (p2.y + p3.y);
        }

        float inv = __frcp_rn(ssum);
        // H = log(S) - (sum s*log s)/S
        float ent = __logf(ssum) - slsum * inv;

        float4 rv = make_float4(s0 * inv, s1 * inv, s2 * inv, s3 * inv);
        reinterpret_cast<float4*>(rank_out)[t * ROWS_PER_THREAD + r] = rv;

        rt4[r] = upper * __frcp_rn(1.0f + __expf(-rate * (ent - midpoint)));
    }

    reinterpret_cast<float4*>(rt_out)[t] =
        make_float4(rt4[0], rt4[1], rt4[2], rt4[3]);
}

extern "C" void kernel_launch(void* const* d_in, const int* in_sizes, int n_in,
                              void* d_out, int out_size) {
    const int* stim = (const int*)d_in[0];
    const float* table = (const float*)d_in[1];
    const float* w = (const float*)d_in[2];
    const float* rho_p = (const float*)d_in[3];
    const float* beta_p = (const float*)d_in[4];
    const float* tau_p = (const float*)d_in[5];
    const float* gamma_p = (const float*)d_in[6];
    const float* upper_p = (const float*)d_in[7];
    const float* midpoint_p = (const float*)d_in[8];
    const float* rate_p = (const float*)d_in[9];

    int B = in_sizes[0] / 5;
    float* rank_out = (float*)d_out;                 // B*4
    float* rt_out = (float*)d_out + (size_t)B * 4;   // B

    int n_threads = B / ROWS_PER_THREAD;             // B divisible by 4
    int block = 256;
    int grid = (n_threads + block - 1) / block;
    rankrt_kernel<<<grid, block>>>(
        (const int4*)stim, table, w, rho_p, beta_p, tau_p, gamma_p,
        upper_p, midpoint_p, rate_p, rank_out, rt_out, n_threads);
}